// round 7
// baseline (speedup 1.0000x reference)
#include <cuda_runtime.h>
#include <cuda_fp16.h>

#define NN 100000
#define EE 1600000
#define GG 128
#define SCAN_B 1024
#define SCAN_NBLK ((NN + SCAN_B - 1) / SCAN_B)   // 98
#define GR 128   // gemm rows per block
#define SIS 132  // sInT stride (multiple of 4 -> 16B-aligned float4 rows)

// ---------------- scratch (static device globals; no allocation) ----------------
__device__ __align__(16) unsigned long long g_degcnt[NN]; // count<<48 | wdeg*2^32
__device__ __align__(16) float g_dinv[NN];
__device__ __align__(16) int   g_offs[NN + 1];
__device__ __align__(16) int   g_cursor[NN];
__device__ __align__(16) int   g_bsum[SCAN_NBLK + 1];
__device__ __align__(16) int2  g_payload[EE];            // {src, (w*dinv[src])-as-bits} sorted by dest
__device__ __align__(16) __half g_bufA[(size_t)NN * 64]; // h (gemm output, fp16)
__device__ __align__(16) __half g_bufC[(size_t)NN * 64]; // conv output layers 1-2 (fp16)
__device__ __align__(16) float g_bufB[(size_t)NN * 64];  // conv output layer 3 (fp32, pooled)
__device__ __align__(16) float g_pooled[GG * 64];
__device__ __align__(16) float g_bnsc[3][64];
__device__ __align__(16) float g_bnsh[3][64];

struct BNParams { const float* p[12]; };  // (gamma,beta,mean,var) x 3 layers

__device__ __forceinline__ unsigned long long ffma2(unsigned long long a,
                                                    unsigned long long b,
                                                    unsigned long long c) {
    unsigned long long d;
    asm("fma.rn.f32x2 %0, %1, %2, %3;" : "=l"(d) : "l"(a), "l"(b), "l"(c));
    return d;
}
__device__ __forceinline__ unsigned long long rep2(float a) {
    unsigned long long d;
    unsigned ai = __float_as_uint(a);
    asm("mov.b64 %0, {%1, %1};" : "=l"(d) : "r"(ai));
    return d;
}

// ---------------- prep ----------------
__global__ void k_prep(BNParams bp) {
    int i = blockIdx.x * blockDim.x + threadIdx.x;
    if (i < NN) g_degcnt[i] = 1ULL << 32;      // self-loop weight 1.0 fixed-point, count 0
    if (i < GG * 64) g_pooled[i] = 0.0f;
    if (i < 3 * 64) {
        int l = i >> 6, f = i & 63;
        const float* ga = bp.p[l * 4 + 0];
        const float* be = bp.p[l * 4 + 1];
        const float* mn = bp.p[l * 4 + 2];
        const float* va = bp.p[l * 4 + 3];
        float sc = ga[f] * rsqrtf(va[f] + 1e-5f);
        g_bnsc[l][f] = sc;
        g_bnsh[l][f] = be[f] - mn[f] * sc;
    }
}

// per-edge: one packed 64-bit atomic (count + fixed-point weighted degree)
__global__ void k_degcount(const int* __restrict__ col, const float* __restrict__ w) {
    int e = blockIdx.x * blockDim.x + threadIdx.x;
    if (e >= EE) return;
    unsigned long long pack = (1ULL << 48) + (unsigned long long)(w[e] * 4294967296.0f);
    atomicAdd(&g_degcnt[col[e]], pack);
}

// ---------------- scan phase 1: warp-shfl block scan ----------------
__global__ void k_scan1() {
    __shared__ int ws[32];
    int t = threadIdx.x;
    int lane = t & 31, w = t >> 5;
    int i = blockIdx.x * SCAN_B + t;
    int val = (i < NN) ? (int)(g_degcnt[i] >> 48) : 0;
    int x = val;
#pragma unroll
    for (int off = 1; off < 32; off <<= 1) {
        int y = __shfl_up_sync(0xFFFFFFFFu, x, off);
        if (lane >= off) x += y;
    }
    if (lane == 31) ws[w] = x;
    __syncthreads();
    if (w == 0) {
        int s = ws[lane];
#pragma unroll
        for (int off = 1; off < 32; off <<= 1) {
            int y = __shfl_up_sync(0xFFFFFFFFu, s, off);
            if (lane >= off) s += y;
        }
        ws[lane] = s;          // inclusive warp-sum scan
    }
    __syncthreads();
    int base = (w == 0) ? 0 : ws[w - 1];
    if (i < NN) g_offs[i] = base + x - val;       // exclusive
    if (t == SCAN_B - 1) g_bsum[blockIdx.x] = ws[31];
}

// phase 2: single-warp shfl scan over 98 block sums
__global__ void k_scan2() {
    int t = threadIdx.x;          // 32 threads
    int carry = 0;
    for (int base = 0; base < SCAN_NBLK; base += 32) {
        int i = base + t;
        int v = (i < SCAN_NBLK) ? g_bsum[i] : 0;
        int x = v;
#pragma unroll
        for (int off = 1; off < 32; off <<= 1) {
            int y = __shfl_up_sync(0xFFFFFFFF, x, off);
            if (t >= off) x += y;
        }
        if (i < SCAN_NBLK) g_bsum[i] = carry + x - v;   // exclusive
        carry += __shfl_sync(0xFFFFFFFF, x, 31);
    }
}

// add block offsets, init cursor, finalize dinv, set sentinel
__global__ void k_fix() {
    int i = blockIdx.x * blockDim.x + threadIdx.x;
    if (i < NN) {
        int o = g_offs[i] + g_bsum[i >> 10];
        g_offs[i] = o;
        g_cursor[i] = o;
        float deg = (float)(g_degcnt[i] & 0xFFFFFFFFFFFFULL) * (1.0f / 4294967296.0f);
        g_dinv[i] = rsqrtf(deg);
    }
    if (i == 0) g_offs[NN] = EE;
}

// scatter edges into dest-sorted order; payload = {src, w*dinv[src]}
__global__ void k_scatter(const int* __restrict__ row, const int* __restrict__ col,
                          const float* __restrict__ w) {
    int e = blockIdx.x * blockDim.x + threadIdx.x;
    if (e >= EE) return;
    int r = row[e];
    int c = col[e];
    float nv = g_dinv[r] * w[e];
    int pos = atomicAdd(&g_cursor[c], 1);
    g_payload[pos] = make_int2(r, __float_as_int(nv));
}

// ---------------- register-blocked GEMM with packed f32x2 FMA ----------------
// 128 threads, tile GR=128 rows x 64 cols; micro 8 rows x 8 cols per thread.
// epilogue: bufA (fp16 h) only.  IN16: input is fp16 (g_bufC)
template <int ACT, int IN16>
__device__ __forceinline__ void gemm_body(const void* __restrict__ in_,
                                          const float* __restrict__ W, int l) {
    __shared__ __align__(16) float sW[64 * 64];          // [k][c]
    __shared__ __align__(16) float sInT[64 * SIS];       // [k][r], padded (SIS % 4 == 0)
    int t = threadIdx.x;  // 128

    const float4* W4 = (const float4*)W;
    float4* sW4 = (float4*)sW;
#pragma unroll
    for (int i = 0; i < 8; i++) sW4[t + 128 * i] = W4[t + 128 * i];

    int r0 = blockIdx.x * GR;
    if (IN16) {
        const __half* in = (const __half*)in_;
#pragma unroll
        for (int i = 0; i < 8; i++) {
            int idx = t + 128 * i;       // 0..1023 uint4s (8 halves each)
            int rr = idx >> 3;
            int cc = (idx & 7) * 8;
            int gr = r0 + rr;
            uint4 v = make_uint4(0, 0, 0, 0);
            if (gr < NN) v = *(const uint4*)(in + (size_t)gr * 64 + cc);
            float f[8];
            float2 p;
            p = __half22float2(*(__half2*)&v.x); f[0] = p.x; f[1] = p.y;
            p = __half22float2(*(__half2*)&v.y); f[2] = p.x; f[3] = p.y;
            p = __half22float2(*(__half2*)&v.z); f[4] = p.x; f[5] = p.y;
            p = __half22float2(*(__half2*)&v.w); f[6] = p.x; f[7] = p.y;
#pragma unroll
            for (int j = 0; j < 8; j++) {
                float fv = f[j];
                if (ACT == 1) fv = fmaxf(fv, 0.f) * g_bnsc[l][cc + j] + g_bnsh[l][cc + j];
                sInT[(cc + j) * SIS + rr] = fv;
            }
        }
    } else {
        const float* in = (const float*)in_;
#pragma unroll
        for (int i = 0; i < 16; i++) {
            int idx = t + 128 * i;        // 0..2047 float4s in 128x64 tile
            int rr = idx >> 4;
            int cc = (idx & 15) * 4;
            int gr = r0 + rr;
            float4 v = make_float4(0.f, 0.f, 0.f, 0.f);
            if (gr < NN) v = *(const float4*)(in + (size_t)gr * 64 + cc);
            if (ACT == 1) {
                v.x = fmaxf(v.x, 0.f) * g_bnsc[l][cc + 0] + g_bnsh[l][cc + 0];
                v.y = fmaxf(v.y, 0.f) * g_bnsc[l][cc + 1] + g_bnsh[l][cc + 1];
                v.z = fmaxf(v.z, 0.f) * g_bnsc[l][cc + 2] + g_bnsh[l][cc + 2];
                v.w = fmaxf(v.w, 0.f) * g_bnsc[l][cc + 3] + g_bnsh[l][cc + 3];
            }
            sInT[(cc + 0) * SIS + rr] = v.x;
            sInT[(cc + 1) * SIS + rr] = v.y;
            sInT[(cc + 2) * SIS + rr] = v.z;
            sInT[(cc + 3) * SIS + rr] = v.w;
        }
    }
    __syncthreads();

    int tr = t >> 3;                  // 0..15 row group
    int tc = t & 7;                   // 0..7  col group
    int rbase = tr * 8;
    int cbase = tc * 8;

    unsigned long long acc[8][4];
#pragma unroll
    for (int r = 0; r < 8; r++)
#pragma unroll
        for (int j = 0; j < 4; j++) acc[r][j] = 0ull;

#pragma unroll
    for (int k = 0; k < 64; k++) {
        float4 a0 = *(const float4*)&sInT[k * SIS + rbase];
        float4 a1 = *(const float4*)&sInT[k * SIS + rbase + 4];
        ulonglong2 wlo = *(const ulonglong2*)&sW[k * 64 + cbase];
        ulonglong2 whi = *(const ulonglong2*)&sW[k * 64 + cbase + 4];
        unsigned long long ap[8];
        ap[0] = rep2(a0.x); ap[1] = rep2(a0.y); ap[2] = rep2(a0.z); ap[3] = rep2(a0.w);
        ap[4] = rep2(a1.x); ap[5] = rep2(a1.y); ap[6] = rep2(a1.z); ap[7] = rep2(a1.w);
#pragma unroll
        for (int r = 0; r < 8; r++) {
            acc[r][0] = ffma2(ap[r], wlo.x, acc[r][0]);
            acc[r][1] = ffma2(ap[r], wlo.y, acc[r][1]);
            acc[r][2] = ffma2(ap[r], whi.x, acc[r][2]);
            acc[r][3] = ffma2(ap[r], whi.y, acc[r][3]);
        }
    }

#pragma unroll
    for (int r = 0; r < 8; r++) {
        int gr = r0 + rbase + r;
        if (gr >= NN) break;
        float2 c0 = *(float2*)&acc[r][0];
        float2 c1 = *(float2*)&acc[r][1];
        float2 c2 = *(float2*)&acc[r][2];
        float2 c3 = *(float2*)&acc[r][3];
        __half2 h0 = __floats2half2_rn(c0.x, c0.y);
        __half2 h1 = __floats2half2_rn(c1.x, c1.y);
        __half2 h2 = __floats2half2_rn(c2.x, c2.y);
        __half2 h3 = __floats2half2_rn(c3.x, c3.y);
        *(uint4*)&g_bufA[(size_t)gr * 64 + cbase] =
            make_uint4(*(unsigned*)&h0, *(unsigned*)&h1,
                       *(unsigned*)&h2, *(unsigned*)&h3);
    }
}

__global__ void __launch_bounds__(128) k_gemm1(const float* __restrict__ x,
                                               const float* __restrict__ W) {
    gemm_body<0, 0>(x, W, 0);
}
__global__ void __launch_bounds__(128) k_gemm23(const float* __restrict__ W, int l) {
    gemm_body<1, 1>(g_bufC, W, l);
}

// ---------------- CSR aggregation (warp per destination, 4x8 lane groups) ----------------
// out[c] = dinv[c] * sum_e (w_e*dinv[src_e]) * h16[src_e] + dinv[c]^2 * h16[c] + bias
// OUT16=1 -> fp16 to g_bufC (layers 1-2); OUT16=0 -> fp32 to g_bufB (layer 3)
template <int OUT16>
__global__ void __launch_bounds__(256) k_agg(const float* __restrict__ bias) {
    int warp = threadIdx.x >> 5;
    int lane = threadIdx.x & 31;
    int c = blockIdx.x * 8 + warp;          // NN % 8 == 0
    int grp = lane >> 3;                    // 0..3: stride-4 edge groups
    int q = lane & 7;                       // owns halves [8q, 8q+7] = one uint4
    int e = g_offs[c] + grp;
    int end = g_offs[c + 1];

    const uint4* __restrict__ A4 = (const uint4*)g_bufA;   // 8 uint4 per 64-feat row

    float acc[8] = {0.f, 0.f, 0.f, 0.f, 0.f, 0.f, 0.f, 0.f};
    for (; e < end; e += 4) {
        int2 p = __ldg(&g_payload[e]);
        uint4 r = __ldg(&A4[(size_t)p.x * 8 + q]);
        float n = __int_as_float(p.y);
        float2 f;
        f = __half22float2(*(__half2*)&r.x); acc[0] += f.x * n; acc[1] += f.y * n;
        f = __half22float2(*(__half2*)&r.y); acc[2] += f.x * n; acc[3] += f.y * n;
        f = __half22float2(*(__half2*)&r.z); acc[4] += f.x * n; acc[5] += f.y * n;
        f = __half22float2(*(__half2*)&r.w); acc[6] += f.x * n; acc[7] += f.y * n;
    }
#pragma unroll
    for (int j = 0; j < 8; j++) {
        acc[j] += __shfl_xor_sync(0xFFFFFFFFu, acc[j], 8);
        acc[j] += __shfl_xor_sync(0xFFFFFFFFu, acc[j], 16);
    }

    if (grp == 0) {
        float dv = g_dinv[c];
        float snv = dv * dv;
        uint4 sr = __ldg(&A4[(size_t)c * 8 + q]);
        float s[8];
        float2 f;
        f = __half22float2(*(__half2*)&sr.x); s[0] = f.x; s[1] = f.y;
        f = __half22float2(*(__half2*)&sr.y); s[2] = f.x; s[3] = f.y;
        f = __half22float2(*(__half2*)&sr.z); s[4] = f.x; s[5] = f.y;
        f = __half22float2(*(__half2*)&sr.w); s[6] = f.x; s[7] = f.y;
        float4 b0 = *(const float4*)(bias + q * 8);
        float4 b1 = *(const float4*)(bias + q * 8 + 4);
        float o[8];
        o[0] = acc[0] * dv + s[0] * snv + b0.x;
        o[1] = acc[1] * dv + s[1] * snv + b0.y;
        o[2] = acc[2] * dv + s[2] * snv + b0.z;
        o[3] = acc[3] * dv + s[3] * snv + b0.w;
        o[4] = acc[4] * dv + s[4] * snv + b1.x;
        o[5] = acc[5] * dv + s[5] * snv + b1.y;
        o[6] = acc[6] * dv + s[6] * snv + b1.z;
        o[7] = acc[7] * dv + s[7] * snv + b1.w;
        if (OUT16) {
            __half2 h0 = __floats2half2_rn(o[0], o[1]);
            __half2 h1 = __floats2half2_rn(o[2], o[3]);
            __half2 h2 = __floats2half2_rn(o[4], o[5]);
            __half2 h3 = __floats2half2_rn(o[6], o[7]);
            *(uint4*)&g_bufC[(size_t)c * 64 + q * 8] =
                make_uint4(*(unsigned*)&h0, *(unsigned*)&h1,
                           *(unsigned*)&h2, *(unsigned*)&h3);
        } else {
            *(float4*)&g_bufB[(size_t)c * 64 + q * 8]     = make_float4(o[0], o[1], o[2], o[3]);
            *(float4*)&g_bufB[(size_t)c * 64 + q * 8 + 4] = make_float4(o[4], o[5], o[6], o[7]);
        }
    }
}

// ---------------- BN3 + global_add_pool (batch is sorted: run-accumulate) ----------------
#define POOL_CHUNK 128
__global__ void k_pool(const int* __restrict__ batch) {
    int f = threadIdx.x;  // 64 threads: one per feature
    int start = blockIdx.x * POOL_CHUNK;
    int end = start + POOL_CHUNK;
    if (end > NN) end = NN;
    if (start >= NN) return;
    float sc = g_bnsc[2][f], sh = g_bnsh[2][f];
    int cur = batch[start];
    float acc = 0.f;
    for (int n = start; n < end; n++) {
        int b = batch[n];
        if (b != cur) {
            atomicAdd(&g_pooled[cur * 64 + f], acc);
            acc = 0.f;
            cur = b;
        }
        acc += g_bufB[(size_t)n * 64 + f] * sc + sh;
    }
    atomicAdd(&g_pooled[cur * 64 + f], acc);
}

// ---------------- FC: out[g] = relu(pooled[g]) . Wfc + bfc ----------------
__global__ void k_fc(const float* __restrict__ Wfc, const float* __restrict__ bfc,
                     float* __restrict__ out) {
    int g = threadIdx.x;  // 128
    float acc = 0.f;
#pragma unroll
    for (int k = 0; k < 64; k++)
        acc += fmaxf(g_pooled[g * 64 + k], 0.f) * Wfc[k];
    out[g] = acc + bfc[0];
}

// ---------------- launch ----------------
extern "C" void kernel_launch(void* const* d_in, const int* in_sizes, int n_in,
                              void* d_out, int out_size) {
    const float* x     = (const float*)d_in[0];
    const int*   ei    = (const int*)d_in[1];
    const int*   row   = ei;
    const int*   col   = ei + EE;
    const float* ew    = (const float*)d_in[2];
    const int*   batch = (const int*)d_in[3];
    const float* W1 = (const float*)d_in[4];
    const float* b1 = (const float*)d_in[5];
    const float* W2 = (const float*)d_in[6];
    const float* b2 = (const float*)d_in[7];
    const float* W3 = (const float*)d_in[8];
    const float* b3 = (const float*)d_in[9];
    const float* Wfc = (const float*)d_in[10];
    const float* bfc = (const float*)d_in[11];

    BNParams bp;
    for (int i = 0; i < 12; i++) bp.p[i] = (const float*)d_in[12 + i];

    int nb_n = (NN + 255) / 256;          // 391
    int nb_e = (EE + 255) / 256;          // 6250
    int nb_gemm = (NN + GR - 1) / GR;     // 782
    int nb_agg = NN / 8;                  // 12500
    int nb_pool = (NN + POOL_CHUNK - 1) / POOL_CHUNK; // 782

    // CSR build + norm precompute
    k_prep<<<nb_n, 256>>>(bp);
    k_degcount<<<nb_e, 256>>>(col, ew);
    k_scan1<<<SCAN_NBLK, SCAN_B>>>();
    k_scan2<<<1, 32>>>();
    k_fix<<<nb_n, 256>>>();
    k_scatter<<<nb_e, 256>>>(row, col, ew);

    // layer 1
    k_gemm1<<<nb_gemm, 128>>>(x, W1);
    k_agg<1><<<nb_agg, 256>>>(b1);
    // layer 2 (relu + bn1 fused into gemm input)
    k_gemm23<<<nb_gemm, 128>>>(W2, 0);
    k_agg<1><<<nb_agg, 256>>>(b2);
    // layer 3 (relu + bn2 fused into gemm input)
    k_gemm23<<<nb_gemm, 128>>>(W3, 1);
    k_agg<0><<<nb_agg, 256>>>(b3);

    // bn3 (no relu) + pool, then fc
    k_pool<<<nb_pool, 64>>>(batch);
    k_fc<<<1, 128>>>(Wfc, bfc, (float*)d_out);
}